// round 12
// baseline (speedup 1.0000x reference)
#include <cuda_runtime.h>
#include <cuda_bf16.h>
#include <cstdint>

#define C 80
#define SLAB 32                 // items per group-slab (two k16 steps)
#define PITCH 88                // halves per item row (80+8 pad), conflict-free ldmatrix
#define SLAB_BYTES (SLAB * PITCH * 2)   // 5632
#define KSTEP_BYTES (16 * PITCH * 2)    // 2816
#define NTHREADS 128            // 4 warps = 1 group
#define GRID 888                // 6 CTAs/SM x 148

__device__ float g_cooc[C * C];
__device__ unsigned int g_count;

__device__ const int g_pbi[15] = {0,0,0,0, 0,1,1,1, 1,2,2,2, 3,3,4};
__device__ const int g_pbj[15] = {0,1,2,3, 4,1,2,3, 4,2,3,4, 3,4,4};

#define LDSM4T(r, addr) \
    asm volatile("ldmatrix.sync.aligned.m8n8.x4.trans.shared.b16 {%0,%1,%2,%3}, [%4];" \
                 : "=r"((r)[0]), "=r"((r)[1]), "=r"((r)[2]), "=r"((r)[3]) : "r"(addr))

#define MMA16(acc, A, B0, B1) \
    asm volatile("mma.sync.aligned.m16n8k16.row.col.f32.bf16.bf16.f32 " \
                 "{%0,%1,%2,%3}, {%4,%5,%6,%7}, {%8,%9}, {%0,%1,%2,%3};" \
                 : "+f"((acc)[0]), "+f"((acc)[1]), "+f"((acc)[2]), "+f"((acc)[3]) \
                 : "r"((A)[0]), "r"((A)[1]), "r"((A)[2]), "r"((A)[3]), "r"(B0), "r"(B1))

#define PAIR_MMA(P, A, FB) do { \
        MMA16(d[P][0], A, (FB)[0], (FB)[1]); \
        MMA16(d[P][1], A, (FB)[2], (FB)[3]); } while (0)

static __device__ __forceinline__ uint32_t pack_bf16x2(float x, float y) {
    uint32_t r;
    asm("prmt.b32 %0, %1, %2, 0x7632;" : "=r"(r)
        : "r"(__float_as_uint(x)), "r"(__float_as_uint(y)));
    return r;
}

__global__ __launch_bounds__(NTHREADS, 6)
void fused_kernel(const float* __restrict__ label,
                  const float* __restrict__ pre_adj,
                  float* __restrict__ out, int batch) {
    __shared__ __align__(16) __nv_bfloat16 slab[2 * SLAB * PITCH];   // double-buffered
    __shared__ float sRed[15 * 256];
    __shared__ float red[4];
    __shared__ int s_last;

    const int tid  = threadIdx.x;
    const int warp = tid >> 5;       // 0..3
    const int lane = tid & 31;
    const int g    = lane >> 2;
    const int t    = lane & 3;
    const int gi   = lane >> 3;
    const int li   = lane & 7;

    for (int i = tid; i < 15 * 256; i += NTHREADS) sRed[i] = 0.0f;
    __syncthreads();

    const uint32_t smem_u32 = (uint32_t)__cvta_generic_to_shared(slab);

    // ldmatrix per-lane offsets (bytes) within a 16-item k-step window (proven R2-R11)
    const uint32_t a_off = (uint32_t)(((((gi & 2) ? 8 : 0) + li) * PITCH + ((gi & 1) ? 8 : 0)) * 2);
    const uint32_t b_off = (uint32_t)(((((gi & 1) ? 8 : 0) + li) * PITCH + ((gi & 2) ? 8 : 0)) * 2);

    // load/store geometry: warp w fills items w*8 .. w*8+7 (8 items x 20 chunks)
    int goff[5], soff[5];
    #pragma unroll
    for (int p = 0; p < 5; p++) {
        int chunk = lane + p * 32;
        int item  = warp * 8 + chunk / 20;
        int c4    = chunk % 20;
        goff[p] = item * C + c4 * 4;                 // f32 elements
        soff[p] = item * (PITCH * 2) + c4 * 8;       // bytes (bf16: 8B per chunk)
    }

    float d[4][2][4];
    #pragma unroll
    for (int p = 0; p < 4; p++)
        #pragma unroll
        for (int n = 0; n < 2; n++)
            #pragma unroll
            for (int q = 0; q < 4; q++) d[p][n][q] = 0.0f;

    const int numSlabs = (batch + SLAB - 1) / SLAB;
    int s = blockIdx.x;

    float4 st[5];
    if (s < numSlabs) {
        const float* pb = label + (long long)s * SLAB * C;
        const int remc = (batch - s * SLAB) * C;
        #pragma unroll
        for (int p = 0; p < 5; p++)
            st[p] = (goff[p] < remc) ? *(const float4*)(pb + goff[p])
                                     : make_float4(0.f, 0.f, 0.f, 0.f);
    }

    int pbuf = 0;
    while (s < numSlabs) {
        // ---- convert + store own 8 items ----
        const uint32_t sb = smem_u32 + (uint32_t)(pbuf * SLAB_BYTES);
        #pragma unroll
        for (int p = 0; p < 5; p++) {
            uint32_t lo = pack_bf16x2(st[p].x, st[p].y);
            uint32_t hi = pack_bf16x2(st[p].z, st[p].w);
            asm volatile("st.shared.v2.b32 [%0], {%1,%2};"
                         :: "r"(sb + (uint32_t)soff[p]), "r"(lo), "r"(hi) : "memory");
        }

        // ---- prefetch next slab (fire-and-forget) ----
        const int nxt = s + GRID;
        if (nxt < numSlabs) {
            const float* pb = label + (long long)nxt * SLAB * C;
            const int remc = (batch - nxt * SLAB) * C;
            #pragma unroll
            for (int p = 0; p < 5; p++)
                st[p] = (goff[p] < remc) ? *(const float4*)(pb + goff[p])
                                         : make_float4(0.f, 0.f, 0.f, 0.f);
        }

        __syncthreads();   // buf[pbuf] filled; all warps done MMA on buf[pbuf^1]

        // ---- MMA: two k16 steps; 15 block-pairs split 4/4/4/3 ----
        #pragma unroll
        for (int ks = 0; ks < 2; ks++) {
            const uint32_t kb = sb + (uint32_t)(ks * KSTEP_BYTES);
            uint32_t A0[4], A1[4], fb[4];
            if (warp == 0) {
                LDSM4T(A0, kb + a_off + 0 * 32);
                LDSM4T(fb, kb + b_off + 0 * 32); PAIR_MMA(0, A0, fb);   // (0,0)
                LDSM4T(fb, kb + b_off + 1 * 32); PAIR_MMA(1, A0, fb);   // (0,1)
                LDSM4T(fb, kb + b_off + 2 * 32); PAIR_MMA(2, A0, fb);   // (0,2)
                LDSM4T(fb, kb + b_off + 3 * 32); PAIR_MMA(3, A0, fb);   // (0,3)
            } else if (warp == 1) {
                LDSM4T(A0, kb + a_off + 0 * 32);
                LDSM4T(A1, kb + a_off + 1 * 32);
                LDSM4T(fb, kb + b_off + 4 * 32); PAIR_MMA(0, A0, fb);   // (0,4)
                LDSM4T(fb, kb + b_off + 1 * 32); PAIR_MMA(1, A1, fb);   // (1,1)
                LDSM4T(fb, kb + b_off + 2 * 32); PAIR_MMA(2, A1, fb);   // (1,2)
                LDSM4T(fb, kb + b_off + 3 * 32); PAIR_MMA(3, A1, fb);   // (1,3)
            } else if (warp == 2) {
                LDSM4T(A0, kb + a_off + 1 * 32);
                LDSM4T(A1, kb + a_off + 2 * 32);
                LDSM4T(fb, kb + b_off + 4 * 32); PAIR_MMA(0, A0, fb);   // (1,4)
                                                 PAIR_MMA(3, A1, fb);   // (2,4)
                LDSM4T(fb, kb + b_off + 2 * 32); PAIR_MMA(1, A1, fb);   // (2,2)
                LDSM4T(fb, kb + b_off + 3 * 32); PAIR_MMA(2, A1, fb);   // (2,3)
            } else {
                LDSM4T(A0, kb + a_off + 3 * 32);
                LDSM4T(A1, kb + a_off + 4 * 32);
                LDSM4T(fb, kb + b_off + 3 * 32); PAIR_MMA(0, A0, fb);   // (3,3)
                LDSM4T(fb, kb + b_off + 4 * 32); PAIR_MMA(1, A0, fb);   // (3,4)
                                                 PAIR_MMA(2, A1, fb);   // (4,4)
            }
        }

        pbuf ^= 1;
        s = nxt;
    }

    // ---- flush accumulators into per-CTA smem blocks (exact ints) ----
    {
        const int npairs = (warp < 3) ? 4 : 3;
        #pragma unroll
        for (int p = 0; p < 4; p++) {
            if (p >= npairs) break;
            const int slot = (warp * 4 + p) * 256;
            #pragma unroll
            for (int n = 0; n < 2; n++) {
                const int cb = n * 8 + 2 * t;
                atomicAdd(&sRed[slot + (g)     * 16 + cb],     d[p][n][0]);
                atomicAdd(&sRed[slot + (g)     * 16 + cb + 1], d[p][n][1]);
                atomicAdd(&sRed[slot + (g + 8) * 16 + cb],     d[p][n][2]);
                atomicAdd(&sRed[slot + (g + 8) * 16 + cb + 1], d[p][n][3]);
            }
        }
    }
    __syncthreads();

    // ---- one global flush per CTA ----
    for (int idx = tid; idx < 15 * 256; idx += NTHREADS) {
        const int slot = idx >> 8, e = idx & 255;
        const int i = g_pbi[slot] * 16 + (e >> 4);
        const int j = g_pbj[slot] * 16 + (e & 15);
        atomicAdd(&g_cooc[i * C + j], sRed[idx]);
    }

    // ---- last-CTA finalize ----
    __threadfence();
    __syncthreads();
    if (tid == 0)
        s_last = (atomicAdd(&g_count, 1u) == (unsigned)gridDim.x - 1u) ? 1 : 0;
    __syncthreads();
    if (!s_last) return;

    float sum = 0.0f;
    for (int idx = tid; idx < C * C; idx += NTHREADS) {
        int i = idx / C, j = idx - i * C;
        int bi = i >> 4, bj = j >> 4;
        float cooc = (bi <= bj) ? g_cooc[i * C + j] : g_cooc[j * C + i];  // upper blocks stored
        float cnt  = g_cooc[i * C + i];
        float adj  = (i == j) ? 1.0f : __fdividef(cooc, cnt + 1e-7f);
        float r = fabsf(pre_adj[idx] - adj);
        sum += (r < 1.0f) ? (r * r) : (r - 0.5f);
    }
    #pragma unroll
    for (int o = 16; o > 0; o >>= 1) sum += __shfl_down_sync(0xffffffffu, sum, o);
    if (lane == 0) red[warp] = sum;
    __syncthreads();
    if (warp == 0) {
        float v = (lane < 4) ? red[lane] : 0.0f;
        #pragma unroll
        for (int o = 16; o > 0; o >>= 1) v += __shfl_down_sync(0xffffffffu, v, o);
        if (lane == 0) out[0] = v / (float)(C * C);
    }
    __syncthreads();   // all g_cooc reads complete before re-zero
    for (int idx = tid; idx < C * C; idx += NTHREADS) g_cooc[idx] = 0.0f;
    if (tid == 0) g_count = 0u;
}

extern "C" void kernel_launch(void* const* d_in, const int* in_sizes, int n_in,
                              void* d_out, int out_size) {
    const float* pre_adj = (const float*)d_in[0];
    const float* label   = (const float*)d_in[1];
    const int batch = in_sizes[1] / C;

    fused_kernel<<<GRID, NTHREADS>>>(label, pre_adj, (float*)d_out, batch);
}